// round 17
// baseline (speedup 1.0000x reference)
#include <cuda_runtime.h>
#include <cuda_fp16.h>
#include <stdint.h>
#include <math.h>

#define BDIM 4
#define SDIM 4096
#define DDIM 1024

// Scratch (device globals — allocation-free per harness rules)
__device__ __half g_xh  [(size_t)BDIM * SDIM * DDIM];      // x  -> fp16
__device__ __half g_wth [(size_t)3 * DDIM * DDIM];         // W^T [3D, D] fp16
__device__ __half g_qkvh[(size_t)BDIM * SDIM * 3 * DDIM];  // qkv [B*S, 3D] fp16
__device__ float  g_sc  [(size_t)BDIM * SDIM * SDIM];      // scaled scores f32
__device__ __half g_ph  [(size_t)BDIM * SDIM * SDIM];      // attn probs fp16

// ---------------------------------------------------------------------------
// Arch-portable PTX helpers (NO tcgen05 — harness targets sm_103 base)
// ---------------------------------------------------------------------------
__device__ __forceinline__ uint32_t smem_u32(const void* p) {
    uint32_t a;
    asm("{ .reg .u64 t; cvta.to.shared.u64 t, %1; cvt.u32.u64 %0, t; }" : "=r"(a) : "l"(p));
    return a;
}
__device__ __forceinline__ void mma16n8k16(float c[4],
                                           uint32_t a0, uint32_t a1, uint32_t a2, uint32_t a3,
                                           uint32_t b0, uint32_t b1) {
    asm volatile(
        "mma.sync.aligned.m16n8k16.row.col.f32.f16.f16.f32 "
        "{%0,%1,%2,%3}, {%4,%5,%6,%7}, {%8,%9}, {%0,%1,%2,%3};"
        : "+f"(c[0]), "+f"(c[1]), "+f"(c[2]), "+f"(c[3])
        : "r"(a0), "r"(a1), "r"(a2), "r"(a3), "r"(b0), "r"(b1));
}
__device__ __forceinline__ void ldsm4(uint32_t& r0, uint32_t& r1, uint32_t& r2, uint32_t& r3,
                                      uint32_t addr) {
    asm volatile("ldmatrix.sync.aligned.m8n8.x4.shared.b16 {%0,%1,%2,%3}, [%4];"
                 : "=r"(r0), "=r"(r1), "=r"(r2), "=r"(r3) : "r"(addr));
}
__device__ __forceinline__ void ldsm4t(uint32_t& r0, uint32_t& r1, uint32_t& r2, uint32_t& r3,
                                       uint32_t addr) {
    asm volatile("ldmatrix.sync.aligned.m8n8.x4.trans.shared.b16 {%0,%1,%2,%3}, [%4];"
                 : "=r"(r0), "=r"(r1), "=r"(r2), "=r"(r3) : "r"(addr));
}
__device__ __forceinline__ void cpasync16(uint32_t s, const void* g) {
    asm volatile("cp.async.cg.shared.global [%0], [%1], 16;" :: "r"(s), "l"(g));
}
__device__ __forceinline__ void cp_commit() {
    asm volatile("cp.async.commit_group;" ::: "memory");
}
__device__ __forceinline__ void cp_wait0() {
    asm volatile("cp.async.wait_group 0;" ::: "memory");
}

// ---------------------------------------------------------------------------
// TN fp16 GEMM (fp32 accum), templated on B layout:
//   TRANSB=0: B[N,K] row-major (K-major rows)     — QKV / scores
//   TRANSB=1: B[K,N] row-major (natural V layout) — PV, via ldmatrix.trans
// CTA 128x256x128, 256 threads (8 warps = 2M x 4N, warp tile 64x64), 1 CTA/SM.
// 2-stage cp.async pipeline with TKH=128: 8 k-steps (256 warp-MMAs) per
// barrier epoch — half the epochs of the TKH=64 version, amortizing the
// whole-SM sync stall (1 CTA/SM has no co-resident CTA to cover barriers).
// WAR safety: all k-steps of slot t consumed BEFORE the barrier; next tile's
// ks0 fragments prefetched AFTER it from slot t+1 (rewritten only after the
// following barrier). Row strides ≡ 16 mod 128 B: conflict-free LDSM phases.
// ---------------------------------------------------------------------------
#define TM 128
#define TN 256
#define TKH 128
#define ROWP 136                                 // A / B(N-major) row pad, halves
#define ROWPB 264                                // B(trans) row pad, halves (528 B)
#define A_TILE (128 * ROWP * 2)                  // 34816 B
#define B_TILE_N (256 * ROWP * 2)                // 69632 B  (TRANSB=0)
#define B_TILE_T (128 * ROWPB * 2)               // 67584 B  (TRANSB=1)
#define NSTAGE 2
#define SMEM_MAX (NSTAGE * (A_TILE + B_TILE_N))  // 208896 B

extern __shared__ uint32_t smu[];

template<int TRANSB>
__device__ __forceinline__ void load_frags(uint32_t aBuf, uint32_t bBuf, int ks,
                                           uint32_t aLane, uint32_t bLane,
                                           uint32_t af[4][4], uint32_t bf[8][2])
{
    const uint32_t aOff = (uint32_t)(ks * 32);
    #pragma unroll
    for (int mb = 0; mb < 4; mb++)
        ldsm4(af[mb][0], af[mb][1], af[mb][2], af[mb][3],
              aBuf + aLane + aOff + (uint32_t)(mb * 16 * ROWP * 2));
    if (TRANSB) {
        const uint32_t bOff = (uint32_t)(ks * 16 * ROWPB * 2);
        #pragma unroll
        for (int q = 0; q < 4; q++)
            ldsm4t(bf[2 * q][0], bf[2 * q][1], bf[2 * q + 1][0], bf[2 * q + 1][1],
                   bBuf + bLane + bOff + (uint32_t)(q * 32));
    } else {
        const uint32_t bOff = (uint32_t)(ks * 32);
        #pragma unroll
        for (int q = 0; q < 4; q++)
            ldsm4(bf[2 * q][0], bf[2 * q][1], bf[2 * q + 1][0], bf[2 * q + 1][1],
                  bBuf + bLane + bOff + (uint32_t)(q * 16 * ROWP * 2));
    }
}

__device__ __forceinline__ void do_mmas(float acc[4][8][4],
                                        uint32_t af[4][4], uint32_t bf[8][2])
{
    #pragma unroll
    for (int mb = 0; mb < 4; mb++)
        #pragma unroll
        for (int nb = 0; nb < 8; nb++)
            mma16n8k16(acc[mb][nb], af[mb][0], af[mb][1], af[mb][2], af[mb][3],
                       bf[nb][0], bf[nb][1]);
}

template<int TRANSB>
__global__ __launch_bounds__(256, 1)
void gemm_f16mma(const __half* __restrict__ A, int lda, long long sA,
                 const __half* __restrict__ B, int ldb, long long sB,
                 void* __restrict__ Cv, int ldc, long long sC,
                 int K, const float* __restrict__ bias, float cmul, int halfOut)
{
    const int tid = threadIdx.x;
    const int wid = tid >> 5, lid = tid & 31;
    const int g = lid >> 2, tq = lid & 3;
    const int wm = wid & 1, wn = wid >> 1;     // warps: 2(M) x 4(N)
    const int bx = blockIdx.x, by = blockIdx.y, bz = blockIdx.z;

    const int B_TILE = TRANSB ? B_TILE_T : B_TILE_N;
    const int STAGE_B = A_TILE + B_TILE;

    A += (long long)bz * sA + (long long)(by * TM) * lda;
    if (TRANSB) B += (long long)bz * sB + bx * TN;                      // B[k][n]
    else        B += (long long)bz * sB + (long long)(bx * TN) * ldb;   // B[n][k]

    const uint32_t sbase = smem_u32(smu);

    // A copy map: 2 threads per row (128 rows), 64 halves each (8 x 16B)
    const int aRow = tid >> 1;
    const int aKof = (tid & 1) * 64;
    const __half* Ap = A + (long long)aRow * lda + aKof;
    const uint32_t aSts = (uint32_t)(aRow * ROWP + aKof) * 2u;
    // B copy map
    const __half* Bp;
    uint32_t bSts;
    if (TRANSB) {   // 128 rows x 512B; 2 threads/row, 256B each (16 x 16B)
        Bp = B + (long long)(tid >> 1) * ldb + (tid & 1) * 128;
        bSts = (uint32_t)((tid >> 1) * ROWPB + (tid & 1) * 128) * 2u;
    } else {        // 256 rows, 1 thread/row, 128 halves (16 x 16B)
        Bp = B + (long long)tid * ldb;
        bSts = (uint32_t)(tid * ROWP) * 2u;
    }

    // ldmatrix lane addressing (byte offsets within a tile)
    const int laneRowA = lid & 15;
    const uint32_t aLane = (uint32_t)((wm * 64 + laneRowA) * ROWP * 2) + ((lid >> 4) << 4);
    uint32_t bLane;
    if (TRANSB) {   // kr = (lid&7)|(lid&8); ncol = wn*64 + 8*(lid>>4) (+q*16 per call)
        const int kr = (lid & 7) | (lid & 8);
        bLane = (uint32_t)(kr * ROWPB * 2) + (uint32_t)((wn * 64 + 8 * (lid >> 4)) * 2);
    } else {
        const int laneRowB = (lid & 7) | ((lid >> 4) << 3);
        bLane = (uint32_t)((wn * 64 + laneRowB) * ROWP * 2) + (((lid >> 3) & 1) << 4);
    }

    float acc[4][8][4];
    #pragma unroll
    for (int i = 0; i < 4; i++)
        #pragma unroll
        for (int j = 0; j < 8; j++)
            #pragma unroll
            for (int r = 0; r < 4; r++) acc[i][j][r] = 0.f;

    const int NK = K / TKH;

    auto stage_copy = [&](int t) {
        const uint32_t dst = sbase + (uint32_t)(t & 1) * STAGE_B;
        const __half* As = Ap + t * TKH;
        #pragma unroll
        for (int i = 0; i < 8; i++) cpasync16(dst + aSts + i * 16, As + i * 8);
        const uint32_t bDst = dst + A_TILE;
        if (TRANSB) {
            const __half* Bs = Bp + (long long)(t * TKH) * ldb;
            #pragma unroll
            for (int i = 0; i < 16; i++) cpasync16(bDst + bSts + i * 16, Bs + i * 8);
        } else {
            const __half* Bs = Bp + t * TKH;
            #pragma unroll
            for (int i = 0; i < 16; i++) cpasync16(bDst + bSts + i * 16, Bs + i * 8);
        }
    };

    // ---- prologue: fill stage 0 ----
    stage_copy(0); cp_commit();
    cp_wait0();
    __syncthreads();

    // Register-alternating fragments
    uint32_t af[2][4][4], bf[2][8][2];
    load_frags<TRANSB>(sbase, sbase + A_TILE, 0, aLane, bLane, af[0], bf[0]);

    for (int t = 0; t < NK; ++t) {
        if (t + 1 < NK) stage_copy(t + 1);
        cp_commit();

        const uint32_t aBuf = sbase + (uint32_t)(t & 1) * STAGE_B;
        const uint32_t bBuf = aBuf + A_TILE;

        // 8 k-steps, all consumed before the barrier (2-stage WAR safety)
        #pragma unroll
        for (int ks = 0; ks < 7; ks++) {
            load_frags<TRANSB>(aBuf, bBuf, ks + 1, aLane, bLane,
                               af[(ks + 1) & 1], bf[(ks + 1) & 1]);
            do_mmas(acc, af[ks & 1], bf[ks & 1]);
        }
        do_mmas(acc, af[1], bf[1]);                       // ks7

        cp_wait0();               // stage t+1 resident
        __syncthreads();          // all warps done reading slot t

        if (t + 1 < NK) {
            const uint32_t aN = sbase + (uint32_t)((t + 1) & 1) * STAGE_B;
            load_frags<TRANSB>(aN, aN + A_TILE, 0, aLane, bLane, af[0], bf[0]);
        }
    }

    // ---- epilogue ----
    float badd[8][2];
    #pragma unroll
    for (int nb = 0; nb < 8; nb++) {
        const int col = wn * 64 + nb * 8 + tq * 2;
        badd[nb][0] = bias ? __ldg(bias + bx * TN + col)     : 0.f;
        badd[nb][1] = bias ? __ldg(bias + bx * TN + col + 1) : 0.f;
    }
    if (halfOut) {
        __half* C = (__half*)Cv + (long long)bz * sC + (long long)(by * TM) * ldc + bx * TN;
        #pragma unroll
        for (int mb = 0; mb < 4; mb++) {
            const int row = wm * 64 + mb * 16 + g;
            #pragma unroll
            for (int nb = 0; nb < 8; nb++) {
                const int col = wn * 64 + nb * 8 + tq * 2;
                __half2 v0 = __floats2half2_rn(fmaf(acc[mb][nb][0], cmul, badd[nb][0]),
                                               fmaf(acc[mb][nb][1], cmul, badd[nb][1]));
                __half2 v1 = __floats2half2_rn(fmaf(acc[mb][nb][2], cmul, badd[nb][0]),
                                               fmaf(acc[mb][nb][3], cmul, badd[nb][1]));
                *(__half2*)(C + (long long)row * ldc + col)       = v0;
                *(__half2*)(C + (long long)(row + 8) * ldc + col) = v1;
            }
        }
    } else {
        float* C = (float*)Cv + (long long)bz * sC + (long long)(by * TM) * ldc + bx * TN;
        #pragma unroll
        for (int mb = 0; mb < 4; mb++) {
            const int row = wm * 64 + mb * 16 + g;
            #pragma unroll
            for (int nb = 0; nb < 8; nb++) {
                const int col = wn * 64 + nb * 8 + tq * 2;
                *(float2*)(C + (long long)row * ldc + col) =
                    make_float2(fmaf(acc[mb][nb][0], cmul, badd[nb][0]),
                                fmaf(acc[mb][nb][1], cmul, badd[nb][1]));
                *(float2*)(C + (long long)(row + 8) * ldc + col) =
                    make_float2(fmaf(acc[mb][nb][2], cmul, badd[nb][0]),
                                fmaf(acc[mb][nb][3], cmul, badd[nb][1]));
            }
        }
    }
}

// ---------------------------------------------------------------------------
// Elementwise f32 -> fp16 (for x). Grid-stride float4 -> 2x half2.
// ---------------------------------------------------------------------------
__global__ void f32_to_h_kernel(const float* __restrict__ in, __half* __restrict__ out,
                                size_t n4)
{
    size_t i = (size_t)blockIdx.x * blockDim.x + threadIdx.x;
    size_t stride = (size_t)gridDim.x * blockDim.x;
    for (; i < n4; i += stride) {
        float4 v = ((const float4*)in)[i];
        __half2* o = (__half2*)(out + i * 4);
        o[0] = __floats2half2_rn(v.x, v.y);
        o[1] = __floats2half2_rn(v.z, v.w);
    }
}

// ---------------------------------------------------------------------------
// Transpose f32 -> fp16: out[c][r] = h(in[r][c]).  (for W^T)
// ---------------------------------------------------------------------------
__global__ void transpose_f2h(const float* __restrict__ in, int ldin,
                              __half* __restrict__ out, int ldout)
{
    __shared__ float tile[32][33];
    const int c0 = blockIdx.x << 5;
    const int r0 = blockIdx.y << 5;
    const int x = threadIdx.x, y = threadIdx.y;     // 32 x 8
    #pragma unroll
    for (int j = 0; j < 32; j += 8)
        tile[y + j][x] = in[(long long)(r0 + y + j) * ldin + c0 + x];
    __syncthreads();
    #pragma unroll
    for (int j = 0; j < 32; j += 8)
        out[(long long)(c0 + y + j) * ldout + r0 + x] = __float2half_rn(tile[x][y + j]);
}

// ---------------------------------------------------------------------------
// Row softmax over 4096 pre-scaled f32 scores; writes fp16 probabilities.
// ---------------------------------------------------------------------------
__device__ __forceinline__ float warpMax(float v) {
    #pragma unroll
    for (int o = 16; o > 0; o >>= 1) v = fmaxf(v, __shfl_xor_sync(0xffffffffu, v, o));
    return v;
}
__device__ __forceinline__ float warpSum(float v) {
    #pragma unroll
    for (int o = 16; o > 0; o >>= 1) v += __shfl_xor_sync(0xffffffffu, v, o);
    return v;
}

__global__ __launch_bounds__(256, 4)
void softmax4096(const float* __restrict__ s, __half* __restrict__ pOut)
{
    const float* p = s + (long long)blockIdx.x * 4096;
    __half* po = pOut + (long long)blockIdx.x * 4096;
    const int t = threadIdx.x;
    const int lane = t & 31, wid = t >> 5;
    __shared__ float red[8];

    float4 v[4];
    #pragma unroll
    for (int i = 0; i < 4; i++) v[i] = *(const float4*)(p + i * 1024 + t * 4);

    float m = v[0].x;
    #pragma unroll
    for (int i = 0; i < 4; i++) {
        m = fmaxf(m, v[i].x); m = fmaxf(m, v[i].y);
        m = fmaxf(m, v[i].z); m = fmaxf(m, v[i].w);
    }
    m = warpMax(m);
    if (lane == 0) red[wid] = m;
    __syncthreads();
    m = red[0];
    #pragma unroll
    for (int j = 1; j < 8; j++) m = fmaxf(m, red[j]);

    float sum = 0.f;
    #pragma unroll
    for (int i = 0; i < 4; i++) {
        v[i].x = __expf(v[i].x - m); v[i].y = __expf(v[i].y - m);
        v[i].z = __expf(v[i].z - m); v[i].w = __expf(v[i].w - m);
        sum += v[i].x + v[i].y + v[i].z + v[i].w;
    }
    sum = warpSum(sum);
    __syncthreads();
    if (lane == 0) red[wid] = sum;
    __syncthreads();
    float tot = red[0];
    #pragma unroll
    for (int j = 1; j < 8; j++) tot += red[j];
    const float inv = 1.0f / tot;

    #pragma unroll
    for (int i = 0; i < 4; i++) {
        __half2* o = (__half2*)(po + i * 1024 + t * 4);
        o[0] = __floats2half2_rn(v[i].x * inv, v[i].y * inv);
        o[1] = __floats2half2_rn(v[i].z * inv, v[i].w * inv);
    }
}

// ---------------------------------------------------------------------------
// Launch
// ---------------------------------------------------------------------------
extern "C" void kernel_launch(void* const* d_in, const int* in_sizes, int n_in,
                              void* d_out, int out_size)
{
    (void)in_sizes; (void)n_in; (void)out_size;
    const float* x = (const float*)d_in[0];   // [B,S,D]
    const float* W = (const float*)d_in[1];   // [D,3D]
    const float* b = (const float*)d_in[2];   // [3D]
    float* out = (float*)d_out;               // [B,S,D]

    __half *xh, *wth, *qkvh, *ph;
    float *sc;
    cudaGetSymbolAddress((void**)&xh,   g_xh);
    cudaGetSymbolAddress((void**)&wth,  g_wth);
    cudaGetSymbolAddress((void**)&qkvh, g_qkvh);
    cudaGetSymbolAddress((void**)&sc,   g_sc);
    cudaGetSymbolAddress((void**)&ph,   g_ph);

    cudaFuncSetAttribute(gemm_f16mma<0>, cudaFuncAttributeMaxDynamicSharedMemorySize, SMEM_MAX);
    cudaFuncSetAttribute(gemm_f16mma<1>, cudaFuncAttributeMaxDynamicSharedMemorySize, SMEM_MAX);

    // 0a) xh = fp16(x)
    f32_to_h_kernel<<<1024, 256>>>(x, xh, (size_t)BDIM * SDIM * DDIM / 4);

    // 0b) Wth[e][d] = fp16(W[d][e])
    transpose_f2h<<<dim3(3 * DDIM / 32, DDIM / 32, 1), dim3(32, 8)>>>(
        W, 3 * DDIM, wth, DDIM);

    // 1) qkvh = fp16(xh @ Wth^T + b)   (M=16384, N=3072, K=1024)
    gemm_f16mma<0><<<dim3(3 * DDIM / TN, BDIM * SDIM / TM, 1), 256, SMEM_MAX>>>(
        xh,   DDIM, 0LL,
        wth,  DDIM, 0LL,
        qkvh, 3 * DDIM, 0LL,
        DDIM, b, 1.0f, 1);

    // 2) scores = (Q @ K^T) * 1/32   (per batch: M=4096, N=4096, K=1024), f32
    gemm_f16mma<0><<<dim3(SDIM / TN, SDIM / TM, BDIM), 256, SMEM_MAX>>>(
        qkvh,        3 * DDIM, (long long)SDIM * 3 * DDIM,
        qkvh + DDIM, 3 * DDIM, (long long)SDIM * 3 * DDIM,
        sc,          SDIM,     (long long)SDIM * SDIM,
        DDIM, (const float*)0, 0.03125f, 0);

    // 3) softmax rows: f32 scaled scores -> fp16 probs
    softmax4096<<<BDIM * SDIM, 256>>>(sc, ph);

    // 4) out = P @ V   (per batch: M=4096, N=1024, K=4096), V read in natural
    //    [s][d] layout directly from qkvh via ldmatrix.trans, f32 out
    gemm_f16mma<1><<<dim3(DDIM / TN, SDIM / TM, BDIM), 256, SMEM_MAX>>>(
        ph,              SDIM,     (long long)SDIM * SDIM,
        qkvh + 2 * DDIM, 3 * DDIM, (long long)SDIM * 3 * DDIM,
        out,             DDIM,     (long long)SDIM * DDIM,
        SDIM, (const float*)0, 1.0f, 0);
}